// round 14
// baseline (speedup 1.0000x reference)
#include <cuda_runtime.h>

#define NW 14
#define NSTATE (1 << NW)        // 16384 amplitudes
#define NTHREADS 1024
#define NWARPS (NTHREADS / 32)

// ==================== compile-time GF(2) machinery ====================
struct CT {
    unsigned rowA[NW];      // rows of A
    unsigned colAinv[NW];   // columns of A^-1 (pair masks)
    unsigned cw[NW];        // rowA2[13-w]: measurement parity masks per wire
    unsigned swzA[32];      // swz(combos of colAinv[5..9])  (p0 store offsets)
    unsigned swzB[16];      // swz(combos of colAinv[0..3])  (final-pass offsets)
    int fw4[NW];            // 4-bit WHT frequency per wire
};

constexpr unsigned ctswz(unsigned y) { return y ^ ((y >> 4) & 0xFu); }
constexpr int ctpar(unsigned v) { int p = 0; while (v) { p ^= (int)(v & 1u); v >>= 1; } return p; }

constexpr CT buildCT() {
    CT g{};
    unsigned R[NW] = {};
    for (int j = 0; j < NW; ++j) R[j] = 1u << j;
    // CNOT(w,w+1) w=0..12 then CNOT(13,0); wire w <-> bit 13-w
    for (int w = 0; w < NW - 1; ++w) R[NW - 2 - w] ^= R[NW - 1 - w];
    R[NW - 1] ^= R[0];
    for (int j = 0; j < NW; ++j) g.rowA[j] = R[j];
    unsigned aug[NW] = {};
    for (int j = 0; j < NW; ++j) aug[j] = R[j] | (1u << (NW + j));
    for (int col = 0; col < NW; ++col) {
        int piv = -1;
        for (int rr = col; rr < NW; ++rr)
            if ((aug[rr] >> col) & 1u) { piv = rr; break; }
        unsigned t = aug[col]; aug[col] = aug[piv]; aug[piv] = t;
        for (int rr = 0; rr < NW; ++rr)
            if (rr != col && ((aug[rr] >> col) & 1u)) aug[rr] ^= aug[col];
    }
    for (int bc = 0; bc < NW; ++bc) {
        unsigned mc = 0;
        for (int j = 0; j < NW; ++j) mc |= ((aug[j] >> (NW + bc)) & 1u) << j;
        g.colAinv[bc] = mc;
    }
    for (int w = 0; w < NW; ++w) {
        const int k = 13 - w;
        unsigned rr = 0;
        for (int j = 0; j < NW; ++j) if ((R[k] >> j) & 1u) rr ^= R[j];
        g.cw[w] = rr;
    }
    for (unsigned u = 0; u < 32; ++u) {
        unsigned M = 0;
        for (int i = 0; i < 5; ++i) if ((u >> i) & 1u) M ^= g.colAinv[5 + i];
        g.swzA[u] = ctswz(M);
    }
    for (unsigned u = 0; u < 16; ++u) {
        unsigned M = 0;
        for (int i = 0; i < 4; ++i) if ((u >> i) & 1u) M ^= g.colAinv[i];
        g.swzB[u] = ctswz(M);
    }
    for (int w = 0; w < NW; ++w) {
        int f = 0;
        for (int i = 0; i < 4; ++i) f |= ctpar(g.colAinv[i] & g.cw[w]) << i;
        g.fw4[w] = f;
    }
    return g;
}
constexpr CT CD = buildCT();

// ---- compile-time validation ----
constexpr bool checkPass(unsigned posmask, int b0, int k) {
    unsigned v[NW] = {}; int n = 0;
    for (int p = 0; p < NW; ++p) if ((posmask >> p) & 1u) v[n++] = 1u << p;
    for (int i = 0; i < k; ++i) v[n++] = CD.colAinv[b0 + i];
    if (n != NW) return false;
    int rank = 0;
    for (int bit = 0; bit < NW; ++bit) {
        int piv = -1;
        for (int i = rank; i < NW; ++i) if ((v[i] >> bit) & 1u) { piv = i; break; }
        if (piv < 0) continue;
        unsigned t = v[rank]; v[rank] = v[piv]; v[piv] = t;
        for (int i = 0; i < NW; ++i) if (i != rank && ((v[i] >> bit) & 1u)) v[i] ^= v[rank];
        ++rank;
    }
    return rank == NW;
}
static_assert(checkPass(0x001F, 5, 9), "p0 transversal (bits 0..4 + gates 5..13)");
static_assert(checkPass(0x3FF0, 0, 4), "final transversal (bits 4..13 + gates 0..3)");
static_assert(CD.colAinv[4] == 0x18 && CD.colAinv[5] == 0x30 && CD.colAinv[6] == 0x60 &&
              CD.colAinv[7] == 0xC0 && CD.colAinv[8] == 0x180 && CD.colAinv[9] == 0x300 &&
              CD.colAinv[10] == 0x600 && CD.colAinv[11] == 0xC00 &&
              CD.colAinv[12] == 0x1800 && CD.colAinv[13] == 0x3000, "chain masks");
static_assert((CD.rowA[5] & 0x1F) == 0 && (CD.rowA[6] & 0x1F) == 0 && (CD.rowA[7] & 0x1F) == 0 &&
              (CD.rowA[8] & 0x1F) == 0 && (CD.rowA[9] & 0x1F) == 0 && (CD.rowA[10] & 0x1F) == 0 &&
              (CD.rowA[11] & 0x1F) == 0 && (CD.rowA[12] & 0x1F) == 0 &&
              (CD.rowA[13] & 0x1F) == 0x1F, "table bases");
static_assert((CD.rowA[0] & 0x3FF0) == 0x3FF0 && (CD.rowA[1] & 0x3FF0) == 0x3FF0 &&
              (CD.rowA[2] & 0x3FF0) == 0x3FF0 && (CD.rowA[3] & 0x3FF0) == 0x3FF0, "final bases");

template<int V> struct IC { static constexpr int v = V; };

// ==================== device helpers ====================
__device__ __forceinline__ float2 cmul(float2 a, float2 b) {
    return make_float2(fmaf(a.x, b.x, -a.y * b.y), fmaf(a.x, b.y, a.y * b.x));
}
__device__ __forceinline__ float2 cmadd(float2 acc, float2 a, float2 b) {
    acc.x = fmaf(a.x, b.x, fmaf(-a.y, b.y, acc.x));
    acc.y = fmaf(a.x, b.y, fmaf(a.y, b.x, acc.y));
    return acc;
}
__device__ __forceinline__ int dswz(int y) { return y ^ ((y >> 4) & 0xF); }

__device__ __forceinline__ void bfly(float2& a0, float2& a1,
                                     float2 E00, float2 E01, float2 E10, float2 E11) {
    float2 n0 = cmul(E00, a0); n0 = cmadd(n0, E01, a1);
    float2 n1 = cmul(E10, a0); n1 = cmadd(n1, E11, a1);
    a0 = n0; a1 = n1;
}
__device__ __forceinline__ float2 shflx(float2 v, int m) {
    float2 o;
    o.x = __shfl_xor_sync(0xFFFFFFFFu, v.x, m);
    o.y = __shfl_xor_sync(0xFFFFFFFFu, v.y, m);
    return o;
}

// Pass-0 store with folded gate-4: amp = SA*T[u][v] + SB*T[u][v^2]
template<int HALF, int J>
__device__ __forceinline__ void p0_st(float2* st, int zb, float2 SA, float2 SB,
                                      const float2* tab, int v) {
    const float2 t1 = tab[4 * J + v];
    const float2 t2 = tab[4 * J + (v ^ 2)];
    float2 a = cmul(SA, t1); a = cmadd(a, SB, t2);
    st[zb ^ IC<(int)CD.swzA[HALF * 16 + J]>::v] = a;
    if constexpr (J < 15) p0_st<HALF, J + 1>(st, zb, SA, SB, tab, v);
}
// Final-pass load
template<int J>
__device__ __forceinline__ void f_ld(float2 (&amp)[16], const float2* st, int zb) {
    amp[J] = st[zb ^ IC<(int)CD.swzB[J]>::v];
    if constexpr (J < 15) f_ld<J + 1>(amp, st, zb);
}
// signword over rep = cc<<4: bit w = parity(cc & (cw[w]>>4))
template<int W>
__device__ __forceinline__ int signw4(int cc) {
    int v = (__popc(cc & IC<(int)(CD.cw[W] >> 4)>::v) & 1) << W;
    if constexpr (W > 0) v |= signw4<W - 1>(cc);
    return v;
}
// per-wire reduce: tv = +/- Wv[fw4[w]], warp-sum, lane0 stores
template<int W>
__device__ __forceinline__ void redw(float (*wsum)[NW], int swv, const float (&Wv)[16],
                                     int lane, int warp) {
    float tv = Wv[IC<CD.fw4[W]>::v];
    tv = __int_as_float(__float_as_int(tv) ^ ((((unsigned)swv >> W) & 1u) << 31));
#pragma unroll
    for (int off = 16; off; off >>= 1) tv += __shfl_down_sync(0xFFFFFFFFu, tv, off);
    if (lane == 0) wsum[warp][W] = tv;
    if constexpr (W < NW - 1) redw<W + 1>(wsum, swv, Wv, lane, warp);
}

// ==================== kernel ====================
__global__ __launch_bounds__(NTHREADS, 1)
void qsim_kernel(const float* __restrict__ x, const float* __restrict__ params,
                 float* __restrict__ out)
{
    extern __shared__ float2 state[];      // 16384 float2 = 128 KB (also build scratch)
    __shared__ float2 m0V[NW][4];          // layer-0 fused 2x2 (incl. x)
    __shared__ float2 m1V[NW][4];          // layer-1 fused 2x2
    __shared__ float2 T[512][4];           // hoisted-gate table: [u][a*2+p]
    __shared__ float wsum[NWARPS][NW];

    const int tid = threadIdx.x;
    const int b = blockIdx.x;

    // ---- fused gate matrices: M = RX * RZ * RY (layer 0 folds in x)
    if (tid < 2 * NW) {
        const int l = tid / NW, w = tid % NW;
        const float* pp = params + (l * NW + w) * 3;
        float th = pp[0] + (l == 0 ? x[b * NW + w] : 0.0f);
        float s, c;   sincosf(0.5f * th, &s, &c);
        float sz, cz; sincosf(0.5f * pp[1], &sz, &cz);
        float sx, cx; sincosf(0.5f * pp[2], &sx, &cx);
        float2 r00 = make_float2(c * cz, -c * sz);
        float2 r01 = make_float2(-s * cz, s * sz);
        float2 r10 = make_float2(s * cz, s * sz);
        float2 r11 = make_float2(c * cz, c * sz);
        float2 (*dst)[4] = (l == 0) ? m0V : m1V;
        dst[w][0] = make_float2(cx * r00.x + sx * r10.y, cx * r00.y - sx * r10.x);
        dst[w][1] = make_float2(cx * r01.x + sx * r11.y, cx * r01.y - sx * r11.x);
        dst[w][2] = make_float2(sx * r00.y + cx * r10.x, -sx * r00.x + cx * r10.y);
        dst[w][3] = make_float2(sx * r01.y + cx * r11.x, -sx * r01.x + cx * r11.y);
    }
    __syncthreads();

    // ---- Table build: u = tid&511, a-variant = tid>>9 (encoding of y4 = u0^r4).
    //      Encoding over y bits 4..13, then 9 gate stages (wires 8..0) in u-space.
    {
        const int u = tid & 511, a = tid >> 9;
        const int u0 = u & 1, u1 = (u >> 1) & 1, u2 = (u >> 2) & 1, u3 = (u >> 3) & 1,
                  u4 = (u >> 4) & 1, u5 = (u >> 5) & 1, u6 = (u >> 6) & 1,
                  u7 = (u >> 7) & 1, u8 = (u >> 8) & 1;
        float2 cc = m0V[8][(u0 ^ u1) ? 2 : 0];
        cc = cmul(cc, m0V[7][(u1 ^ u2) ? 2 : 0]);
        cc = cmul(cc, m0V[6][(u2 ^ u3) ? 2 : 0]);
        cc = cmul(cc, m0V[5][(u3 ^ u4) ? 2 : 0]);
        cc = cmul(cc, m0V[4][(u4 ^ u5) ? 2 : 0]);
        cc = cmul(cc, m0V[3][(u5 ^ u6) ? 2 : 0]);
        cc = cmul(cc, m0V[2][(u6 ^ u7) ? 2 : 0]);
        cc = cmul(cc, m0V[1][(u7 ^ u8) ? 2 : 0]);
        cc = cmul(cc, m0V[0][u8 ? 2 : 0]);
        cc = cmul(cc, m0V[9][(u0 ^ a) ? 2 : 0]);
        // stages 0..4: in-warp shuffle butterflies (u bits 0..4 = lane bits)
#pragma unroll
        for (int k = 0; k < 5; ++k) {
            const int w = 8 - k;
            const float2 other = shflx(cc, 1 << k);
            const int hi = (u >> k) & 1;
            const float2 Er0 = m1V[w][hi ? 2 : 0];
            const float2 Er1 = m1V[w][hi ? 3 : 1];
            const float2 f1 = hi ? other : cc;
            const float2 f2 = hi ? cc : other;
            float2 n = cmul(Er0, f1); n = cmadd(n, Er1, f2);
            cc = n;
        }
        // stages 5..7: cross-warp via scratch in `state`
#pragma unroll
        for (int k = 5; k < 8; ++k) {
            __syncthreads();
            state[tid] = cc;
            __syncthreads();
            const float2 other = state[tid ^ (1 << k)];
            const int w = 8 - k;
            const int hi = (u >> k) & 1;
            const float2 Er0 = m1V[w][hi ? 2 : 0];
            const float2 Er1 = m1V[w][hi ? 3 : 1];
            const float2 f1 = hi ? other : cc;
            const float2 f2 = hi ? cc : other;
            float2 n = cmul(Er0, f1); n = cmadd(n, Er1, f2);
            cc = n;
        }
        // stage 8 (gate 13, wire 0): fork p variants (label swap by parity(r))
        __syncthreads();
        state[tid] = cc;
        __syncthreads();
        {
            const float2 other = state[tid ^ 256];
            const int hi = u8;
            const float2 f1 = hi ? other : cc;
            const float2 f2 = hi ? cc : other;
            const int i0 = hi ? 2 : 0, i1 = hi ? 3 : 1;
            float2 n = cmul(m1V[0][i0], f1); n = cmadd(n, m1V[0][i1], f2);
            float2 sv = cmul(m1V[0][i0 ^ 3], f1); sv = cmadd(sv, m1V[0][i1 ^ 3], f2);
            T[u][a * 2] = n;
            T[u][a * 2 + 1] = sv;
        }
    }
    __syncthreads();

    // ---- Pass 0: gate 4 (wire 9) folded into a local 2-term table combo.
    //      state[y] = SA*T[u][r4,p] + SB*T[u][r4^1,p]; 10 of 14 gates now applied.
    {
        const int r = tid & 31, h = (tid >> 5) & 15, half = tid >> 9;
        const int p = __popc(r) & 1;
        const int su = __popc(r & IC<(int)CD.rowA[4]>::v) & 1;  // role of y in gate-4 pair
        const int r3 = (r >> 3) & 1, r4 = (r >> 4) & 1;
        float2 B = cmul(m0V[13][(r & 1) ? 2 : 0], m0V[12][(r & 2) ? 2 : 0]);
        B = cmul(B, m0V[11][(r & 4) ? 2 : 0]);
        const float2 Pa = cmul(B, m0V[10][r3 ? 2 : 0]);   // self prefactor (bits 0..3)
        const float2 Pb = cmul(B, m0V[10][r3 ? 0 : 2]);   // partner (bit 3 flipped)
        const float2 Ea = m1V[9][su ? 3 : 0];             // row by role
        const float2 Eb = m1V[9][su ? 2 : 1];
        const float2 SA = cmul(Ea, Pa), SB = cmul(Eb, Pb);
        int Mh = 0;
        if (h & 1) Mh ^= IC<(int)CD.colAinv[10]>::v;
        if (h & 2) Mh ^= IC<(int)CD.colAinv[11]>::v;
        if (h & 4) Mh ^= IC<(int)CD.colAinv[12]>::v;
        if (h & 8) Mh ^= IC<(int)CD.colAinv[13]>::v;
        const int zb = dswz(r ^ Mh);
        const int v = r4 * 2 + p;
        const float2* tab = &T[0][0] + ((((h << 5) | (half << 4))) << 2);
        if (half) p0_st<1, 0>(state, zb, SA, SB, tab, v);
        else      p0_st<0, 0>(state, zb, SA, SB, tab, v);
    }
    __syncthreads();

    // ---- Final pass: gates 0..3 (wires 13..10) + measurement; one coset/thread.
    {
        const int cc = tid;                    // coset rep: y bits 4..13
        const int zb = dswz(cc << 4);
        const int sw = (__popc(cc) & 1) ? 3 : 0;   // shared base swap (rowA[0..3])
        float2 amp[16];
        f_ld<0>(amp, state, zb);
#pragma unroll
        for (int i = 0; i < 4; ++i) {
            const int w = 13 - i;
            const float2 E00 = m1V[w][0 ^ sw], E01 = m1V[w][1 ^ sw];
            const float2 E10 = m1V[w][2 ^ sw], E11 = m1V[w][3 ^ sw];
#pragma unroll
            for (int u = 0; u < 16; ++u) {
                if (u & (1 << i)) continue;
                bfly(amp[u], amp[u | (1 << i)], E00, E01, E10, E11);
            }
        }
        float Wv[16];
#pragma unroll
        for (int u = 0; u < 16; ++u)
            Wv[u] = fmaf(amp[u].x, amp[u].x, amp[u].y * amp[u].y);
        // 16-point WHT
#pragma unroll
        for (int d = 1; d < 16; d <<= 1) {
#pragma unroll
            for (int u = 0; u < 16; ++u) {
                if (u & d) continue;
                const float a = Wv[u], bb = Wv[u | d];
                Wv[u] = a + bb; Wv[u | d] = a - bb;
            }
        }
        const int swv = signw4<NW - 1>(cc);
        const int lane = tid & 31, warp = tid >> 5;
        redw<0>(wsum, swv, Wv, lane, warp);
    }
    __syncthreads();

    if (tid < NW) {
        float s = 0.0f;
#pragma unroll
        for (int q = 0; q < NWARPS; ++q) s += wsum[q][tid];
        out[b * NW + tid] = s;
    }
}

// ==================== host side ====================
extern "C" void kernel_launch(void* const* d_in, const int* in_sizes, int n_in,
                              void* d_out, int out_size)
{
    int i_x = 0, i_p = 1;
    if (n_in >= 2 && in_sizes[0] == 2 * NW * 3) { i_x = 1; i_p = 0; }
    const float* x = (const float*)d_in[i_x];
    const float* params = (const float*)d_in[i_p];
    float* out = (float*)d_out;

    const int batch = in_sizes[i_x] / NW;

    cudaFuncSetAttribute(qsim_kernel, cudaFuncAttributeMaxDynamicSharedMemorySize,
                         NSTATE * sizeof(float2));
    qsim_kernel<<<batch, NTHREADS, NSTATE * sizeof(float2)>>>(x, params, out);
}

// round 16
// speedup vs baseline: 1.1512x; 1.1512x over previous
#include <cuda_runtime.h>

#define NW 14
#define NSTATE (1 << NW)        // 16384 amplitudes
#define NTHREADS 1024
#define NWARPS (NTHREADS / 32)

// ==================== compile-time GF(2) machinery ====================
struct CT {
    unsigned rowA[NW];      // rows of A
    unsigned colAinv[NW];   // columns of A^-1 (pair masks)
    unsigned cw[NW];        // rowA2[13-w]: measurement parity masks per wire
    unsigned swzA16[16];    // swz(combos of colAinv[4..7])  (p0 store offsets, u low bits)
    unsigned swzB[16];      // swz(combos of colAinv[0..3])  (final-pass offsets)
    int fw4[NW];            // 4-bit WHT frequency per wire
};

constexpr unsigned ctswz(unsigned y) { return y ^ ((y >> 4) & 0xFu); }
constexpr int ctpar(unsigned v) { int p = 0; while (v) { p ^= (int)(v & 1u); v >>= 1; } return p; }

constexpr CT buildCT() {
    CT g{};
    unsigned R[NW] = {};
    for (int j = 0; j < NW; ++j) R[j] = 1u << j;
    // CNOT(w,w+1) w=0..12 then CNOT(13,0); wire w <-> bit 13-w
    for (int w = 0; w < NW - 1; ++w) R[NW - 2 - w] ^= R[NW - 1 - w];
    R[NW - 1] ^= R[0];
    for (int j = 0; j < NW; ++j) g.rowA[j] = R[j];
    unsigned aug[NW] = {};
    for (int j = 0; j < NW; ++j) aug[j] = R[j] | (1u << (NW + j));
    for (int col = 0; col < NW; ++col) {
        int piv = -1;
        for (int rr = col; rr < NW; ++rr)
            if ((aug[rr] >> col) & 1u) { piv = rr; break; }
        unsigned t = aug[col]; aug[col] = aug[piv]; aug[piv] = t;
        for (int rr = 0; rr < NW; ++rr)
            if (rr != col && ((aug[rr] >> col) & 1u)) aug[rr] ^= aug[col];
    }
    for (int bc = 0; bc < NW; ++bc) {
        unsigned mc = 0;
        for (int j = 0; j < NW; ++j) mc |= ((aug[j] >> (NW + bc)) & 1u) << j;
        g.colAinv[bc] = mc;
    }
    for (int w = 0; w < NW; ++w) {
        const int k = 13 - w;
        unsigned rr = 0;
        for (int j = 0; j < NW; ++j) if ((R[k] >> j) & 1u) rr ^= R[j];
        g.cw[w] = rr;
    }
    for (unsigned j = 0; j < 16; ++j) {
        unsigned M = 0;
        for (int i = 0; i < 4; ++i) if ((j >> i) & 1u) M ^= g.colAinv[4 + i];
        g.swzA16[j] = ctswz(M);
    }
    for (unsigned u = 0; u < 16; ++u) {
        unsigned M = 0;
        for (int i = 0; i < 4; ++i) if ((u >> i) & 1u) M ^= g.colAinv[i];
        g.swzB[u] = ctswz(M);
    }
    for (int w = 0; w < NW; ++w) {
        int f = 0;
        for (int i = 0; i < 4; ++i) f |= ctpar(g.colAinv[i] & g.cw[w]) << i;
        g.fw4[w] = f;
    }
    return g;
}
constexpr CT CD = buildCT();

// ---- compile-time validation ----
constexpr bool checkPass(unsigned posmask, int b0, int k) {
    unsigned v[NW] = {}; int n = 0;
    for (int p = 0; p < NW; ++p) if ((posmask >> p) & 1u) v[n++] = 1u << p;
    for (int i = 0; i < k; ++i) v[n++] = CD.colAinv[b0 + i];
    if (n != NW) return false;
    int rank = 0;
    for (int bit = 0; bit < NW; ++bit) {
        int piv = -1;
        for (int i = rank; i < NW; ++i) if ((v[i] >> bit) & 1u) { piv = i; break; }
        if (piv < 0) continue;
        unsigned t = v[rank]; v[rank] = v[piv]; v[piv] = t;
        for (int i = 0; i < NW; ++i) if (i != rank && ((v[i] >> bit) & 1u)) v[i] ^= v[rank];
        ++rank;
    }
    return rank == NW;
}
static_assert(checkPass(0x000F, 4, 10), "p0 transversal (bits 0..3 + gates 4..13)");
static_assert(checkPass(0x3FF0, 0, 4), "final transversal (bits 4..13 + gates 0..3)");
// chain masks: colAinv[4+i] = bits {3+i, 4+i}
static_assert(CD.colAinv[4] == 0x18 && CD.colAinv[5] == 0x30 && CD.colAinv[6] == 0x60 &&
              CD.colAinv[7] == 0xC0 && CD.colAinv[8] == 0x180 && CD.colAinv[9] == 0x300 &&
              CD.colAinv[10] == 0x600 && CD.colAinv[11] == 0xC00 &&
              CD.colAinv[12] == 0x1800 && CD.colAinv[13] == 0x3000, "chain masks");
// base parities over complement bits 0..3: gates 4..12 zero, gate 13 = parity(r)
static_assert((CD.rowA[4] & 0xF) == 0 && (CD.rowA[5] & 0xF) == 0 && (CD.rowA[6] & 0xF) == 0 &&
              (CD.rowA[7] & 0xF) == 0 && (CD.rowA[8] & 0xF) == 0 && (CD.rowA[9] & 0xF) == 0 &&
              (CD.rowA[10] & 0xF) == 0 && (CD.rowA[11] & 0xF) == 0 &&
              (CD.rowA[12] & 0xF) == 0 && (CD.rowA[13] & 0xF) == 0xF, "table bases");
// final gates 0..3: bases = parity over bits 4..13
static_assert((CD.rowA[0] & 0x3FF0) == 0x3FF0 && (CD.rowA[1] & 0x3FF0) == 0x3FF0 &&
              (CD.rowA[2] & 0x3FF0) == 0x3FF0 && (CD.rowA[3] & 0x3FF0) == 0x3FF0, "final bases");

template<int V> struct IC { static constexpr int v = V; };

// ==================== device helpers ====================
__device__ __forceinline__ float2 cmul(float2 a, float2 b) {
    return make_float2(fmaf(a.x, b.x, -a.y * b.y), fmaf(a.x, b.y, a.y * b.x));
}
__device__ __forceinline__ float2 cmadd(float2 acc, float2 a, float2 b) {
    acc.x = fmaf(a.x, b.x, fmaf(-a.y, b.y, acc.x));
    acc.y = fmaf(a.x, b.y, fmaf(a.y, b.x, acc.y));
    return acc;
}
__device__ __forceinline__ int dswz(int y) { return y ^ ((y >> 4) & 0xF); }
// swizzled flat index into Tb: f = (u<<2)|slot, folded by bits 4..7 -> 0..3.
__device__ __forceinline__ int tix(int u, int slot) {
    const int f = (u << 2) | slot;
    return f ^ ((f >> 4) & 0xF);
}

__device__ __forceinline__ void bfly(float2& a0, float2& a1,
                                     float2 E00, float2 E01, float2 E10, float2 E11) {
    float2 n0 = cmul(E00, a0); n0 = cmadd(n0, E01, a1);
    float2 n1 = cmul(E10, a0); n1 = cmadd(n1, E11, a1);
    a0 = n0; a1 = n1;
}

// p0 store: state[zb ^ swzA16[J]] = P * Tb[tix((h<<4)|J, v)]
// tix expansion: f = (h<<6)|(J<<2)|v;  x = (f>>4)&0xF = ((h&3)<<2)|(J>>2)
//   -> idx = (h<<6) + ((J<<2) ^ ((h&3)<<2)) + (v ^ (J>>2))
// with hb = h<<6, hx = (h&3)<<2 hoisted.
template<int J>
__device__ __forceinline__ void p0_st(float2* st, int zb, float2 P,
                                      const float2* Tb, int hb, int hx, int v) {
    const float2 t = Tb[hb + (IC<(J << 2)>::v ^ hx) + (v ^ IC<(J >> 2)>::v)];
    st[zb ^ IC<(int)CD.swzA16[J]>::v] = cmul(P, t);
    if constexpr (J < 15) p0_st<J + 1>(st, zb, P, Tb, hb, hx, v);
}
// Final-pass load
template<int J>
__device__ __forceinline__ void f_ld(float2 (&amp)[16], const float2* st, int zb) {
    amp[J] = st[zb ^ IC<(int)CD.swzB[J]>::v];
    if constexpr (J < 15) f_ld<J + 1>(amp, st, zb);
}
// signword over rep = cc<<4
template<int W>
__device__ __forceinline__ int signw4(int cc) {
    int v = (__popc(cc & IC<(int)(CD.cw[W] >> 4)>::v) & 1) << W;
    if constexpr (W > 0) v |= signw4<W - 1>(cc);
    return v;
}
// per-wire reduce: tv = +/- Wv[fw4[w]], warp-sum, lane0 stores
template<int W>
__device__ __forceinline__ void redw(float (*wsum)[NW], int swv, const float (&Wv)[16],
                                     int lane, int warp) {
    float tv = Wv[IC<CD.fw4[W]>::v];
    tv = __int_as_float(__float_as_int(tv) ^ ((((unsigned)swv >> W) & 1u) << 31));
#pragma unroll
    for (int off = 16; off; off >>= 1) tv += __shfl_down_sync(0xFFFFFFFFu, tv, off);
    if (lane == 0) wsum[warp][W] = tv;
    if constexpr (W < NW - 1) redw<W + 1>(wsum, swv, Wv, lane, warp);
}

// ==================== kernel ====================
__global__ __launch_bounds__(NTHREADS, 1)
void qsim_kernel(const float* __restrict__ x, const float* __restrict__ params,
                 float* __restrict__ out)
{
    extern __shared__ float2 state[];      // 16384 float2 = 128 KB
    __shared__ float2 m0V[NW][4];          // layer-0 fused 2x2 (incl. x)
    __shared__ float2 m1V[NW][4];          // layer-1 fused 2x2
    __shared__ float2 Tb[4096];            // hoisted-gate table: 1024 u x {r3,p}
    __shared__ float wsum[NWARPS][NW];

    const int tid = threadIdx.x;
    const int b = blockIdx.x;

    // ---- fused gate matrices: M = RX * RZ * RY (layer 0 folds in x)
    if (tid < 2 * NW) {
        const int l = tid / NW, w = tid % NW;
        const float* pp = params + (l * NW + w) * 3;
        float th = pp[0] + (l == 0 ? x[b * NW + w] : 0.0f);
        float s, c;   sincosf(0.5f * th, &s, &c);
        float sz, cz; sincosf(0.5f * pp[1], &sz, &cz);
        float sx, cx; sincosf(0.5f * pp[2], &sx, &cx);
        float2 r00 = make_float2(c * cz, -c * sz);
        float2 r01 = make_float2(-s * cz, s * sz);
        float2 r10 = make_float2(s * cz, s * sz);
        float2 r11 = make_float2(c * cz, c * sz);
        float2 (*dst)[4] = (l == 0) ? m0V : m1V;
        dst[w][0] = make_float2(cx * r00.x + sx * r10.y, cx * r00.y - sx * r10.x);
        dst[w][1] = make_float2(cx * r01.x + sx * r11.y, cx * r01.y - sx * r11.x);
        dst[w][2] = make_float2(sx * r00.y + cx * r10.x, -sx * r00.x + cx * r10.y);
        dst[w][3] = make_float2(sx * r01.y + cx * r11.x, -sx * r01.x + cx * r11.y);
    }
    __syncthreads();

    // ---- Table build, step 1: encoding over y bits 3..13 for u = tid.
    //      y3 = r3^u0 (wire 10, r3-variant), y4 = u0^u1 (wire 9), ..., y13 = u9 (wire 0).
    {
        const int u = tid;
        const int u0 = u & 1, u1 = (u >> 1) & 1, u2 = (u >> 2) & 1, u3 = (u >> 3) & 1,
                  u4 = (u >> 4) & 1, u5 = (u >> 5) & 1, u6 = (u >> 6) & 1,
                  u7 = (u >> 7) & 1, u8 = (u >> 8) & 1, u9 = (u >> 9) & 1;
        float2 cc = m0V[9][(u0 ^ u1) ? 2 : 0];
        cc = cmul(cc, m0V[8][(u1 ^ u2) ? 2 : 0]);
        cc = cmul(cc, m0V[7][(u2 ^ u3) ? 2 : 0]);
        cc = cmul(cc, m0V[6][(u3 ^ u4) ? 2 : 0]);
        cc = cmul(cc, m0V[5][(u4 ^ u5) ? 2 : 0]);
        cc = cmul(cc, m0V[4][(u5 ^ u6) ? 2 : 0]);
        cc = cmul(cc, m0V[3][(u6 ^ u7) ? 2 : 0]);
        cc = cmul(cc, m0V[2][(u7 ^ u8) ? 2 : 0]);
        cc = cmul(cc, m0V[1][(u8 ^ u9) ? 2 : 0]);
        cc = cmul(cc, m0V[0][u9 ? 2 : 0]);
        Tb[tix(u, 0)] = cmul(m0V[10][u0 ? 2 : 0], cc);   // r3 = 0
        Tb[tix(u, 2)] = cmul(m0V[10][u0 ? 0 : 2], cc);   // r3 = 1
    }

    // ---- step 2: gate stages k=0..8 (gates 4..12, wires 9-k), no label swap.
    //      One pair per thread: a = r3 variant, pu = pair index.
    for (int k = 0; k < 9; ++k) {
        __syncthreads();
        const int a = tid & 1, pu = tid >> 1;
        const int low = pu & ((1 << k) - 1);
        const int u0p = ((pu >> k) << (k + 1)) | low;
        const int u1p = u0p | (1 << k);
        const int i0 = tix(u0p, a * 2), i1 = tix(u1p, a * 2);
        float2 A0 = Tb[i0], A1 = Tb[i1];
        const int w = 9 - k;
        bfly(A0, A1, m1V[w][0], m1V[w][1], m1V[w][2], m1V[w][3]);
        Tb[i0] = A0; Tb[i1] = A1;
    }
    // ---- step 3: gate 13 (u bit 9, wire 0) with p-fork (label swap variants).
    __syncthreads();
    {
        const int a = tid & 1, pu = tid >> 1;             // pu: u bits 0..8
        const int i0 = tix(pu, a * 2), i1 = tix(pu | 512, a * 2);
        const float2 e0 = Tb[i0], e1 = Tb[i1];
        float2 n0 = cmul(m1V[0][0], e0); n0 = cmadd(n0, m1V[0][1], e1);
        float2 n1 = cmul(m1V[0][2], e0); n1 = cmadd(n1, m1V[0][3], e1);
        float2 s0 = cmul(m1V[0][3], e0); s0 = cmadd(s0, m1V[0][2], e1);
        float2 s1 = cmul(m1V[0][1], e0); s1 = cmadd(s1, m1V[0][0], e1);
        Tb[i0] = n0; Tb[i1] = n1;
        Tb[tix(pu, a * 2 + 1)] = s0; Tb[tix(pu | 512, a * 2 + 1)] = s1;
    }
    __syncthreads();

    // ---- Pass 0: state[y] = P_r * T[u][r3, p]  (10 of 14 gates in the table)
    {
        const int r = tid & 15, h = tid >> 4;             // r: y bits 0..3; h: u bits 4..9
        const int p = __popc(r) & 1;                      // gate-13 base = parity(r)
        const int r3 = (r >> 3) & 1;
        const int v = r3 * 2 + p;
        const float2 P = cmul(cmul(m0V[13][(r & 1) ? 2 : 0], m0V[12][(r & 2) ? 2 : 0]),
                              m0V[11][(r & 4) ? 2 : 0]);
        int Mh = 0;
        if (h & 1)  Mh ^= IC<(int)CD.colAinv[8]>::v;
        if (h & 2)  Mh ^= IC<(int)CD.colAinv[9]>::v;
        if (h & 4)  Mh ^= IC<(int)CD.colAinv[10]>::v;
        if (h & 8)  Mh ^= IC<(int)CD.colAinv[11]>::v;
        if (h & 16) Mh ^= IC<(int)CD.colAinv[12]>::v;
        if (h & 32) Mh ^= IC<(int)CD.colAinv[13]>::v;
        const int zb = dswz(r ^ Mh);
        const int hb = h << 6;                            // tix base (CORRECTED: h<<6)
        const int hx = (h & 3) << 2;                      // swizzle fold of h into J field
        p0_st<0>(state, zb, P, Tb, hb, hx, v);
    }
    __syncthreads();

    // ---- Final pass: gates 0..3 (wires 13..10) + measurement; one coset/thread.
    {
        const int cc = tid;                    // coset rep: y bits 4..13
        const int zb = dswz(cc << 4);
        const int sw = (__popc(cc) & 1) ? 3 : 0;   // shared base swap (rowA[0..3])
        float2 amp[16];
        f_ld<0>(amp, state, zb);
#pragma unroll
        for (int i = 0; i < 4; ++i) {
            const int w = 13 - i;
            const float2 E00 = m1V[w][0 ^ sw], E01 = m1V[w][1 ^ sw];
            const float2 E10 = m1V[w][2 ^ sw], E11 = m1V[w][3 ^ sw];
#pragma unroll
            for (int u = 0; u < 16; ++u) {
                if (u & (1 << i)) continue;
                bfly(amp[u], amp[u | (1 << i)], E00, E01, E10, E11);
            }
        }
        float Wv[16];
#pragma unroll
        for (int u = 0; u < 16; ++u)
            Wv[u] = fmaf(amp[u].x, amp[u].x, amp[u].y * amp[u].y);
        // 16-point WHT
#pragma unroll
        for (int d = 1; d < 16; d <<= 1) {
#pragma unroll
            for (int u = 0; u < 16; ++u) {
                if (u & d) continue;
                const float a = Wv[u], bb = Wv[u | d];
                Wv[u] = a + bb; Wv[u | d] = a - bb;
            }
        }
        const int swv = signw4<NW - 1>(cc);
        const int lane = tid & 31, warp = tid >> 5;
        redw<0>(wsum, swv, Wv, lane, warp);
    }
    __syncthreads();

    if (tid < NW) {
        float s = 0.0f;
#pragma unroll
        for (int q = 0; q < NWARPS; ++q) s += wsum[q][tid];
        out[b * NW + tid] = s;
    }
}

// ==================== host side ====================
extern "C" void kernel_launch(void* const* d_in, const int* in_sizes, int n_in,
                              void* d_out, int out_size)
{
    int i_x = 0, i_p = 1;
    if (n_in >= 2 && in_sizes[0] == 2 * NW * 3) { i_x = 1; i_p = 0; }
    const float* x = (const float*)d_in[i_x];
    const float* params = (const float*)d_in[i_p];
    float* out = (float*)d_out;

    const int batch = in_sizes[i_x] / NW;

    cudaFuncSetAttribute(qsim_kernel, cudaFuncAttributeMaxDynamicSharedMemorySize,
                         NSTATE * sizeof(float2));
    qsim_kernel<<<batch, NTHREADS, NSTATE * sizeof(float2)>>>(x, params, out);
}